// round 3
// baseline (speedup 1.0000x reference)
#include <cuda_runtime.h>
#include <cuda_bf16.h>
#include <cstdint>

// ---------------------------------------------------------------------------
// Mamba block forward, fp32 baseline (R2: fix scan grid OOB).
// B=2, L=2048, D_MODEL=1024, D_INNER=2048, D_STATE=16, DT_RANK=64, D_CONV=4
// ---------------------------------------------------------------------------

#define NTOK   4096        // B*L
#define DMODEL 1024
#define DINNER 2048
#define DSTATE 16
#define DTRANK 64
#define XDBL   96          // DT_RANK + 2*D_STATE
#define LSEQ   2048

// scratch (device globals; no allocation allowed)
__device__ float g_xr[(size_t)NTOK * 4096];     // in_proj out: [tok][0:2048]=xs, [2048:4096]=res
__device__ float g_u[(size_t)NTOK * DINNER];    // conv+silu out
__device__ float g_xdbl[(size_t)NTOK * XDBL];   // x_proj out (dt|B|C)
__device__ float g_delta[(size_t)NTOK * DINNER];// dt_proj out -> softplus in-place
__device__ float g_ys[(size_t)NTOK * DINNER];   // scan out
__device__ float g_yg[(size_t)NTOK * DINNER];   // gated out

// ---------------------------------------------------------------------------
// Generic NT SGEMM: C[m,n] = sum_k A[m,k]*B[n,k]
// A: M x K (lda), B: N x K (ldb), C: M x N (ldc).
// M % 128 == 0, K % 16 == 0 assumed. N bounds-checked.
// ---------------------------------------------------------------------------
#define BM 128
#define BN 128
#define BKT 16
#define TM 8
#define TN 8

__global__ __launch_bounds__(256) void sgemm_nt(
    const float* __restrict__ A, const float* __restrict__ B,
    float* __restrict__ C, int M, int N, int K, int lda, int ldb, int ldc)
{
    __shared__ float As[BKT][BM + 4];
    __shared__ float Bs[BKT][BN + 4];

    const int tid = threadIdx.x;
    const int tx = tid & 15;        // 0..15 -> N dir
    const int ty = tid >> 4;        // 0..15 -> M dir
    const int row0 = blockIdx.y * BM;
    const int col0 = blockIdx.x * BN;

    const int lrow = tid >> 2;          // 0..63
    const int lcol = (tid & 3) << 2;    // 0,4,8,12

    float acc[TM][TN];
#pragma unroll
    for (int i = 0; i < TM; ++i)
#pragma unroll
        for (int j = 0; j < TN; ++j) acc[i][j] = 0.f;

    for (int k0 = 0; k0 < K; k0 += BKT) {
        // load A tile (128 x 16)
#pragma unroll
        for (int s = 0; s < 2; ++s) {
            int r = lrow + s * 64;
            const float4 v = *reinterpret_cast<const float4*>(
                A + (size_t)(row0 + r) * lda + k0 + lcol);
            As[lcol + 0][r] = v.x; As[lcol + 1][r] = v.y;
            As[lcol + 2][r] = v.z; As[lcol + 3][r] = v.w;
        }
        // load B tile (128 x 16), N-bounds checked
#pragma unroll
        for (int s = 0; s < 2; ++s) {
            int r = lrow + s * 64;
            int gn = col0 + r;
            float4 v = make_float4(0.f, 0.f, 0.f, 0.f);
            if (gn < N)
                v = *reinterpret_cast<const float4*>(
                    B + (size_t)gn * ldb + k0 + lcol);
            Bs[lcol + 0][r] = v.x; Bs[lcol + 1][r] = v.y;
            Bs[lcol + 2][r] = v.z; Bs[lcol + 3][r] = v.w;
        }
        __syncthreads();

#pragma unroll
        for (int k = 0; k < BKT; ++k) {
            float a[TM], b[TN];
#pragma unroll
            for (int i = 0; i < TM; ++i) a[i] = As[k][ty * TM + i];
#pragma unroll
            for (int j = 0; j < TN; ++j) b[j] = Bs[k][tx * TN + j];
#pragma unroll
            for (int i = 0; i < TM; ++i)
#pragma unroll
                for (int j = 0; j < TN; ++j)
                    acc[i][j] = fmaf(a[i], b[j], acc[i][j]);
        }
        __syncthreads();
    }

#pragma unroll
    for (int i = 0; i < TM; ++i) {
        int gm = row0 + ty * TM + i;
#pragma unroll
        for (int j = 0; j < TN; ++j) {
            int gn = col0 + tx * TN + j;
            if (gn < N) C[(size_t)gm * ldc + gn] = acc[i][j];
        }
    }
}

// ---------------------------------------------------------------------------
// causal depthwise conv (width 4) + bias + SiLU.  xs = g_xr[:, 0:2048]
// ---------------------------------------------------------------------------
__global__ __launch_bounds__(256) void conv_silu_kernel(
    const float* __restrict__ xr, const float* __restrict__ cw,
    const float* __restrict__ cb, float* __restrict__ u)
{
    int idx = blockIdx.x * blockDim.x + threadIdx.x;
    if (idx >= NTOK * DINNER) return;
    int d = idx & (DINNER - 1);
    int m = idx >> 11;            // token index
    int b = m >> 11;              // batch
    int l = m & (LSEQ - 1);

    float w0 = cw[d * 4 + 0], w1 = cw[d * 4 + 1];
    float w2 = cw[d * 4 + 2], w3 = cw[d * 4 + 3];
    float acc = cb[d];
    int base = b << 11;
    if (l >= 3) acc = fmaf(xr[(size_t)(base + l - 3) * 4096 + d], w0, acc);
    if (l >= 2) acc = fmaf(xr[(size_t)(base + l - 2) * 4096 + d], w1, acc);
    if (l >= 1) acc = fmaf(xr[(size_t)(base + l - 1) * 4096 + d], w2, acc);
    acc = fmaf(xr[(size_t)(base + l) * 4096 + d], w3, acc);
    // silu
    u[idx] = acc / (1.f + __expf(-acc));
}

// ---------------------------------------------------------------------------
// delta = softplus(delta_raw + dt_proj_b)
// ---------------------------------------------------------------------------
__global__ __launch_bounds__(256) void softplus_bias_kernel(
    float* __restrict__ delta, const float* __restrict__ bias)
{
    int idx = blockIdx.x * blockDim.x + threadIdx.x;
    if (idx >= NTOK * DINNER) return;
    int d = idx & (DINNER - 1);
    float v = delta[idx] + bias[d];
    float r;
    if (v > 20.f)       r = v;
    else if (v < -20.f) r = __expf(v);
    else                r = log1pf(__expf(v));
    delta[idx] = r;
}

// ---------------------------------------------------------------------------
// selective scan: one thread per (b, d, n); 16 lanes per channel.
// h_l = exp(delta*A_n) * h_{l-1} + delta*u*B_l[n] ;  y_l = sum_n h_l * C_l[n]
// Exactly NTOK*DSTATE = 65536 threads.
// ---------------------------------------------------------------------------
__global__ __launch_bounds__(256) void scan_kernel(
    const float* __restrict__ delta, const float* __restrict__ u,
    const float* __restrict__ xdbl, const float* __restrict__ A_log,
    float* __restrict__ ys)
{
    int gid = blockIdx.x * blockDim.x + threadIdx.x;   // 0..65535
    if (gid >= NTOK * DSTATE) return;
    int n = gid & (DSTATE - 1);
    int ch = gid >> 4;                                  // 0..4095
    int b = ch >> 11;
    int d = ch & (DINNER - 1);

    const float A = -__expf(A_log[d * DSTATE + n]);

    const size_t chanBase = (size_t)(b << 11) * DINNER + d;
    const float* dp = delta + chanBase;
    const float* up = u + chanBase;
    const float* xd = xdbl + (size_t)(b << 11) * XDBL;
    float* yp = ys + chanBase;

    float h = 0.f;
    for (int l = 0; l < LSEQ; ++l) {
        float dl = dp[(size_t)l * DINNER];
        float ul = up[(size_t)l * DINNER];
        float Bv = xd[l * XDBL + DTRANK + n];
        float Cv = xd[l * XDBL + DTRANK + DSTATE + n];
        float dA = __expf(dl * A);
        h = fmaf(dA, h, dl * ul * Bv);
        float v = h * Cv;
#pragma unroll
        for (int off = 8; off; off >>= 1)
            v += __shfl_xor_sync(0xffffffffu, v, off, 16);
        if (n == 0) yp[(size_t)l * DINNER] = v;
    }
}

// ---------------------------------------------------------------------------
// y = (ys + u*D) * silu(res) ;  res = g_xr[:, 2048:4096]
// ---------------------------------------------------------------------------
__global__ __launch_bounds__(256) void gate_kernel(
    const float* __restrict__ ys, const float* __restrict__ u,
    const float* __restrict__ Dp, const float* __restrict__ xr,
    float* __restrict__ yg)
{
    int idx = blockIdx.x * blockDim.x + threadIdx.x;
    if (idx >= NTOK * DINNER) return;
    int d = idx & (DINNER - 1);
    int m = idx >> 11;
    float res = xr[(size_t)m * 4096 + DINNER + d];
    float g = res / (1.f + __expf(-res));
    yg[idx] = (ys[idx] + u[idx] * Dp[d]) * g;
}

// ---------------------------------------------------------------------------
extern "C" void kernel_launch(void* const* d_in, const int* in_sizes, int n_in,
                              void* d_out, int out_size)
{
    const float* x        = (const float*)d_in[0];
    const float* in_w     = (const float*)d_in[1];
    const float* conv_w   = (const float*)d_in[2];
    const float* conv_b   = (const float*)d_in[3];
    const float* xproj_w  = (const float*)d_in[4];
    const float* dtproj_w = (const float*)d_in[5];
    const float* dtproj_b = (const float*)d_in[6];
    const float* A_log    = (const float*)d_in[7];
    const float* Dvec     = (const float*)d_in[8];
    const float* out_w    = (const float*)d_in[9];
    float* out            = (float*)d_out;

    float *xr, *u, *xdbl, *delta, *ys, *yg;
    cudaGetSymbolAddress((void**)&xr,    g_xr);
    cudaGetSymbolAddress((void**)&u,     g_u);
    cudaGetSymbolAddress((void**)&xdbl,  g_xdbl);
    cudaGetSymbolAddress((void**)&delta, g_delta);
    cudaGetSymbolAddress((void**)&ys,    g_ys);
    cudaGetSymbolAddress((void**)&yg,    g_yg);

    const int EW_N = NTOK * DINNER;
    const int EW_BLOCKS = (EW_N + 255) / 256;

    // 1) in_proj: xr = x @ in_w^T   (4096 x 4096 x 1024)
    {
        dim3 grid((4096 + BN - 1) / BN, NTOK / BM);
        sgemm_nt<<<grid, 256>>>(x, in_w, xr, NTOK, 4096, DMODEL,
                                DMODEL, DMODEL, 4096);
    }
    // 2) conv + silu -> u
    conv_silu_kernel<<<EW_BLOCKS, 256>>>(xr, conv_w, conv_b, u);
    // 3) x_proj: xdbl = u @ xproj_w^T   (4096 x 96 x 2048)
    {
        dim3 grid((XDBL + BN - 1) / BN, NTOK / BM);
        sgemm_nt<<<grid, 256>>>(u, xproj_w, xdbl, NTOK, XDBL, DINNER,
                                DINNER, DINNER, XDBL);
    }
    // 4) dt_proj: delta_raw = xdbl[:, :64] @ dtproj_w^T  (4096 x 2048 x 64)
    {
        dim3 grid((DINNER + BN - 1) / BN, NTOK / BM);
        sgemm_nt<<<grid, 256>>>(xdbl, dtproj_w, delta, NTOK, DINNER, DTRANK,
                                XDBL, DTRANK, DINNER);
    }
    // 5) delta = softplus(delta_raw + b)
    softplus_bias_kernel<<<EW_BLOCKS, 256>>>(delta, dtproj_b);
    // 6) selective scan -> ys  (exactly 65536 threads)
    scan_kernel<<<(NTOK * DSTATE) / 256, 256>>>(delta, u, xdbl, A_log, ys);
    // 7) gate -> yg
    gate_kernel<<<EW_BLOCKS, 256>>>(ys, u, Dvec, xr, yg);
    // 8) out_proj: out = yg @ out_w^T  (4096 x 1024 x 2048)
    {
        dim3 grid((DMODEL + BN - 1) / BN, NTOK / BM);
        sgemm_nt<<<grid, 256>>>(yg, out_w, out, NTOK, DMODEL, DINNER,
                                DINNER, DINNER, DMODEL);
    }
}

// round 5
// speedup vs baseline: 1.9186x; 1.9186x over previous
#include <cuda_runtime.h>
#include <cuda_bf16.h>
#include <cstdint>

// ---------------------------------------------------------------------------
// Mamba block forward. R5: GEMMs via mma.sync bf16 hi/lo split (3-MMA),
// cp.async 2-stage pipeline. (tcgen05 rejected: harness targets sm_103 PTX.)
// ---------------------------------------------------------------------------

#define NTOK   4096
#define DMODEL 1024
#define DINNER 2048
#define DSTATE 16
#define DTRANK 64
#define XDBL   96
#define LSEQ   2048

// fp32 scratch
__device__ float g_xr[(size_t)NTOK * 4096];
__device__ float g_u[(size_t)NTOK * DINNER];
__device__ float g_xdbl[(size_t)NTOK * XDBL];
__device__ float g_delta[(size_t)NTOK * DINNER];
__device__ float g_ys[(size_t)NTOK * DINNER];
__device__ float g_yg[(size_t)NTOK * DINNER];

// bf16 hi/lo scratch
__device__ __nv_bfloat16 g_xh[(size_t)NTOK * DMODEL],  g_xl[(size_t)NTOK * DMODEL];
__device__ __nv_bfloat16 g_wih[(size_t)4096 * DMODEL], g_wil[(size_t)4096 * DMODEL];
__device__ __nv_bfloat16 g_uh[(size_t)NTOK * DINNER],  g_ul[(size_t)NTOK * DINNER];
__device__ __nv_bfloat16 g_wxh[(size_t)XDBL * DINNER], g_wxl[(size_t)XDBL * DINNER];
__device__ __nv_bfloat16 g_xdh[(size_t)NTOK * XDBL],   g_xdl[(size_t)NTOK * XDBL];
__device__ __nv_bfloat16 g_wdh[(size_t)DINNER * DTRANK], g_wdl[(size_t)DINNER * DTRANK];
__device__ __nv_bfloat16 g_ygh[(size_t)NTOK * DINNER], g_ygl[(size_t)NTOK * DINNER];
__device__ __nv_bfloat16 g_woh[(size_t)DMODEL * DINNER], g_wol[(size_t)DMODEL * DINNER];

__device__ __forceinline__ uint32_t smem_to_u32(const void* p) {
    uint32_t a;
    asm("{ .reg .u64 t; cvta.to.shared.u64 t, %1; cvt.u32.u64 %0, t; }"
        : "=r"(a) : "l"(p));
    return a;
}

#define CP_ASYNC16(dst, src) \
    asm volatile("cp.async.cg.shared.global [%0], [%1], 16;" :: "r"(dst), "l"(src))
#define CP_COMMIT() asm volatile("cp.async.commit_group;" ::: "memory")
#define CP_WAIT0()  asm volatile("cp.async.wait_group 0;" ::: "memory")
#define CP_WAIT1()  asm volatile("cp.async.wait_group 1;" ::: "memory")

#define LDSM_X4(r0, r1, r2, r3, a) \
    asm volatile("ldmatrix.sync.aligned.m8n8.x4.shared.b16 {%0,%1,%2,%3}, [%4];" \
        : "=r"(r0), "=r"(r1), "=r"(r2), "=r"(r3) : "r"(a))

#define MMA_BF16(d, a, b) \
    asm volatile("mma.sync.aligned.m16n8k16.row.col.f32.bf16.bf16.f32 " \
        "{%0,%1,%2,%3}, {%4,%5,%6,%7}, {%8,%9}, {%0,%1,%2,%3};" \
        : "+f"((d)[0]), "+f"((d)[1]), "+f"((d)[2]), "+f"((d)[3]) \
        : "r"((a)[0]), "r"((a)[1]), "r"((a)[2]), "r"((a)[3]), \
          "r"((b)[0]), "r"((b)[1]))

// swizzled byte offset within a 128x32-bf16 tile (64B rows)
__device__ __forceinline__ uint32_t swoff(int row, int c) {
    return (uint32_t)(row * 64 + ((c ^ ((row >> 1) & 3)) << 4));
}

// ---------------------------------------------------------------------------
// NT GEMM, bf16 hi/lo split: C[m,n] = sum_k A[m,k]*B[n,k] (fp32-ish accuracy)
// block 128x128, warp 64x32, K chunk 32, 2-stage cp.async.
// M = gridDim.y*128. N bounds-checked (B rows clamped, stores guarded).
// K % 32 == 0. lda/ldb % 8 == 0.
// ---------------------------------------------------------------------------
#define GSTAGE 32768              // 4 tiles x 8KB
#define GEMM_SMEM (2 * GSTAGE)

__global__ __launch_bounds__(256) void gemm_mma(
    const __nv_bfloat16* __restrict__ Ah, const __nv_bfloat16* __restrict__ Al,
    const __nv_bfloat16* __restrict__ Bh, const __nv_bfloat16* __restrict__ Bl,
    float* __restrict__ C, int N, int K, int lda, int ldb, int ldc)
{
    extern __shared__ char smem[];
    const uint32_t sb = smem_to_u32(smem);
    const int tid  = threadIdx.x;
    const int wid  = tid >> 5;
    const int lane = tid & 31;
    const int wm = wid & 1;           // 0..1  (64-row slab)
    const int wn = wid >> 1;          // 0..3  (32-col slab)
    const int row0 = blockIdx.y * 128;
    const int col0 = blockIdx.x * 128;

    // per-thread load coords (8 x 16B per stage)
    const int lr = tid >> 2;          // 0..63
    const int lc = tid & 3;           // chunk 0..3

    // ldmatrix lane coords
    const int a_rl = lane & 15;
    const int a_kc = lane >> 4;                         // 0..1
    const int b_rl = (lane & 7) + ((lane >> 4) << 3);   // 0..15
    const int b_kc = (lane >> 3) & 1;

    float acc[4][4][4];
#pragma unroll
    for (int i = 0; i < 4; ++i)
#pragma unroll
        for (int j = 0; j < 4; ++j)
#pragma unroll
            for (int q = 0; q < 4; ++q) acc[i][j][q] = 0.f;

    const int nch = K >> 5;

    // ---- stage loader ----
    auto load_stage = [&](int stage, int k0) {
#pragma unroll
        for (int i = 0; i < 8; ++i) {
            const int tile = i >> 1;                 // 0=Ah 1=Al 2=Bh 3=Bl
            const int r = ((i & 1) << 6) + lr;       // 0..127
            const uint32_t dst = sb + stage * GSTAGE + tile * 8192 + swoff(r, lc);
            const __nv_bfloat16* src;
            if (tile < 2) {
                const __nv_bfloat16* base = tile ? Al : Ah;
                src = base + (size_t)(row0 + r) * lda + k0 + lc * 8;
            } else {
                int gn = col0 + r; if (gn >= N) gn = N - 1;
                const __nv_bfloat16* base = (tile == 2) ? Bh : Bl;
                src = base + (size_t)gn * ldb + k0 + lc * 8;
            }
            CP_ASYNC16(dst, src);
        }
    };

    load_stage(0, 0);
    CP_COMMIT();

    for (int ch = 0; ch < nch; ++ch) {
        if (ch + 1 < nch) {
            load_stage((ch + 1) & 1, (ch + 1) << 5);
            CP_COMMIT();
            CP_WAIT1();
        } else {
            CP_WAIT0();
        }
        __syncthreads();

        const uint32_t st = sb + (ch & 1) * GSTAGE;
#pragma unroll
        for (int ks = 0; ks < 2; ++ks) {
            uint32_t ah[4][4], al[4][4];
#pragma unroll
            for (int mt = 0; mt < 4; ++mt) {
                const int row = wm * 64 + mt * 16 + a_rl;
                const uint32_t ad = st + swoff(row, ks * 2 + a_kc);
                LDSM_X4(ah[mt][0], ah[mt][1], ah[mt][2], ah[mt][3], ad);
                LDSM_X4(al[mt][0], al[mt][1], al[mt][2], al[mt][3], ad + 8192);
            }
            uint32_t bh[2][4], bl[2][4];
#pragma unroll
            for (int p = 0; p < 2; ++p) {
                const int row = wn * 32 + p * 16 + b_rl;
                const uint32_t bd = st + 16384 + swoff(row, ks * 2 + b_kc);
                LDSM_X4(bh[p][0], bh[p][1], bh[p][2], bh[p][3], bd);
                LDSM_X4(bl[p][0], bl[p][1], bl[p][2], bl[p][3], bd + 8192);
            }
#pragma unroll
            for (int mt = 0; mt < 4; ++mt)
#pragma unroll
                for (int nt = 0; nt < 4; ++nt) {
                    uint32_t bfh[2] = { bh[nt >> 1][(nt & 1) * 2],
                                        bh[nt >> 1][(nt & 1) * 2 + 1] };
                    uint32_t bfl[2] = { bl[nt >> 1][(nt & 1) * 2],
                                        bl[nt >> 1][(nt & 1) * 2 + 1] };
                    MMA_BF16(acc[mt][nt], ah[mt], bfh);
                    MMA_BF16(acc[mt][nt], ah[mt], bfl);
                    MMA_BF16(acc[mt][nt], al[mt], bfh);
                }
        }
        __syncthreads();
    }

    // epilogue
#pragma unroll
    for (int mt = 0; mt < 4; ++mt) {
        const int r = row0 + wm * 64 + mt * 16 + (lane >> 2);
#pragma unroll
        for (int nt = 0; nt < 4; ++nt) {
            const int cb = col0 + wn * 32 + nt * 8 + ((lane & 3) << 1);
            if (cb < N) {
                *(float2*)(C + (size_t)r * ldc + cb) =
                    make_float2(acc[mt][nt][0], acc[mt][nt][1]);
                *(float2*)(C + (size_t)(r + 8) * ldc + cb) =
                    make_float2(acc[mt][nt][2], acc[mt][nt][3]);
            }
        }
    }
}

// ---------------------------------------------------------------------------
// fp32 -> (bf16 hi, bf16 lo) split, 4 elems/thread
// ---------------------------------------------------------------------------
__global__ __launch_bounds__(256) void cvt_split(
    const float4* __restrict__ src, __nv_bfloat162* __restrict__ hi,
    __nv_bfloat162* __restrict__ lo, int n4)
{
    int i = blockIdx.x * blockDim.x + threadIdx.x;
    if (i >= n4) return;
    float4 v = src[i];
    __nv_bfloat16 h0 = __float2bfloat16(v.x);
    __nv_bfloat16 h1 = __float2bfloat16(v.y);
    __nv_bfloat16 h2 = __float2bfloat16(v.z);
    __nv_bfloat16 h3 = __float2bfloat16(v.w);
    __nv_bfloat16 l0 = __float2bfloat16(v.x - __bfloat162float(h0));
    __nv_bfloat16 l1 = __float2bfloat16(v.y - __bfloat162float(h1));
    __nv_bfloat16 l2 = __float2bfloat16(v.z - __bfloat162float(h2));
    __nv_bfloat16 l3 = __float2bfloat16(v.w - __bfloat162float(h3));
    hi[2 * i]     = __halves2bfloat162(h0, h1);
    hi[2 * i + 1] = __halves2bfloat162(h2, h3);
    lo[2 * i]     = __halves2bfloat162(l0, l1);
    lo[2 * i + 1] = __halves2bfloat162(l2, l3);
}

// ---------------------------------------------------------------------------
__global__ __launch_bounds__(256) void conv_silu_kernel(
    const float* __restrict__ xr, const float* __restrict__ cw,
    const float* __restrict__ cb, float* __restrict__ u)
{
    int idx = blockIdx.x * blockDim.x + threadIdx.x;
    if (idx >= NTOK * DINNER) return;
    int d = idx & (DINNER - 1);
    int m = idx >> 11;
    int b = m >> 11;
    int l = m & (LSEQ - 1);

    float w0 = cw[d * 4 + 0], w1 = cw[d * 4 + 1];
    float w2 = cw[d * 4 + 2], w3 = cw[d * 4 + 3];
    float acc = cb[d];
    int base = b << 11;
    if (l >= 3) acc = fmaf(xr[(size_t)(base + l - 3) * 4096 + d], w0, acc);
    if (l >= 2) acc = fmaf(xr[(size_t)(base + l - 2) * 4096 + d], w1, acc);
    if (l >= 1) acc = fmaf(xr[(size_t)(base + l - 1) * 4096 + d], w2, acc);
    acc = fmaf(xr[(size_t)(base + l) * 4096 + d], w3, acc);
    u[idx] = acc / (1.f + __expf(-acc));
}

__global__ __launch_bounds__(256) void softplus_bias_kernel(
    float* __restrict__ delta, const float* __restrict__ bias)
{
    int idx = blockIdx.x * blockDim.x + threadIdx.x;
    if (idx >= NTOK * DINNER) return;
    int d = idx & (DINNER - 1);
    float v = delta[idx] + bias[d];
    float r;
    if (v > 20.f)       r = v;
    else if (v < -20.f) r = __expf(v);
    else                r = log1pf(__expf(v));
    delta[idx] = r;
}

__global__ __launch_bounds__(256) void scan_kernel(
    const float* __restrict__ delta, const float* __restrict__ u,
    const float* __restrict__ xdbl, const float* __restrict__ A_log,
    float* __restrict__ ys)
{
    int gid = blockIdx.x * blockDim.x + threadIdx.x;
    if (gid >= NTOK * DSTATE) return;
    int n = gid & (DSTATE - 1);
    int ch = gid >> 4;
    int b = ch >> 11;
    int d = ch & (DINNER - 1);

    const float A = -__expf(A_log[d * DSTATE + n]);
    const size_t chanBase = (size_t)(b << 11) * DINNER + d;
    const float* dp = delta + chanBase;
    const float* up = u + chanBase;
    const float* xd = xdbl + (size_t)(b << 11) * XDBL;
    float* yp = ys + chanBase;

    float h = 0.f;
    for (int l = 0; l < LSEQ; ++l) {
        float dl = dp[(size_t)l * DINNER];
        float ul = up[(size_t)l * DINNER];
        float Bv = xd[l * XDBL + DTRANK + n];
        float Cv = xd[l * XDBL + DTRANK + DSTATE + n];
        float dA = __expf(dl * A);
        h = fmaf(dA, h, dl * ul * Bv);
        float v = h * Cv;
#pragma unroll
        for (int off = 8; off; off >>= 1)
            v += __shfl_xor_sync(0xffffffffu, v, off, 16);
        if (n == 0) yp[(size_t)l * DINNER] = v;
    }
}

__global__ __launch_bounds__(256) void gate_kernel(
    const float* __restrict__ ys, const float* __restrict__ u,
    const float* __restrict__ Dp, const float* __restrict__ xr,
    float* __restrict__ yg)
{
    int idx = blockIdx.x * blockDim.x + threadIdx.x;
    if (idx >= NTOK * DINNER) return;
    int d = idx & (DINNER - 1);
    int m = idx >> 11;
    float res = xr[(size_t)m * 4096 + DINNER + d];
    float g = res / (1.f + __expf(-res));
    yg[idx] = (ys[idx] + u[idx] * Dp[d]) * g;
}

// ---------------------------------------------------------------------------
extern "C" void kernel_launch(void* const* d_in, const int* in_sizes, int n_in,
                              void* d_out, int out_size)
{
    const float* x        = (const float*)d_in[0];
    const float* in_w     = (const float*)d_in[1];
    const float* conv_w   = (const float*)d_in[2];
    const float* conv_b   = (const float*)d_in[3];
    const float* xproj_w  = (const float*)d_in[4];
    const float* dtproj_w = (const float*)d_in[5];
    const float* dtproj_b = (const float*)d_in[6];
    const float* A_log    = (const float*)d_in[7];
    const float* Dvec     = (const float*)d_in[8];
    const float* out_w    = (const float*)d_in[9];
    float* out            = (float*)d_out;

    float *xr, *u, *xdbl, *delta, *ys, *yg;
    cudaGetSymbolAddress((void**)&xr,    g_xr);
    cudaGetSymbolAddress((void**)&u,     g_u);
    cudaGetSymbolAddress((void**)&xdbl,  g_xdbl);
    cudaGetSymbolAddress((void**)&delta, g_delta);
    cudaGetSymbolAddress((void**)&ys,    g_ys);
    cudaGetSymbolAddress((void**)&yg,    g_yg);

    __nv_bfloat16 *xh, *xl, *wih, *wil, *uh, *ul, *wxh, *wxl;
    __nv_bfloat16 *xdh, *xdl, *wdh, *wdl, *ygh, *ygl, *woh, *wol;
    cudaGetSymbolAddress((void**)&xh,  g_xh);  cudaGetSymbolAddress((void**)&xl,  g_xl);
    cudaGetSymbolAddress((void**)&wih, g_wih); cudaGetSymbolAddress((void**)&wil, g_wil);
    cudaGetSymbolAddress((void**)&uh,  g_uh);  cudaGetSymbolAddress((void**)&ul,  g_ul);
    cudaGetSymbolAddress((void**)&wxh, g_wxh); cudaGetSymbolAddress((void**)&wxl, g_wxl);
    cudaGetSymbolAddress((void**)&xdh, g_xdh); cudaGetSymbolAddress((void**)&xdl, g_xdl);
    cudaGetSymbolAddress((void**)&wdh, g_wdh); cudaGetSymbolAddress((void**)&wdl, g_wdl);
    cudaGetSymbolAddress((void**)&ygh, g_ygh); cudaGetSymbolAddress((void**)&ygl, g_ygl);
    cudaGetSymbolAddress((void**)&woh, g_woh); cudaGetSymbolAddress((void**)&wol, g_wol);

    cudaFuncSetAttribute(gemm_mma, cudaFuncAttributeMaxDynamicSharedMemorySize,
                         GEMM_SMEM);

    const int EW_N = NTOK * DINNER;
    const int EW_BLOCKS = (EW_N + 255) / 256;
#define CVT(src, hi, lo, n) \
    cvt_split<<<(n) / 1024, 256>>>((const float4*)(src), (__nv_bfloat162*)(hi), \
                                   (__nv_bfloat162*)(lo), (n) / 4)

    // 1) in_proj: xr = x @ in_w^T   (4096 x 4096 x 1024)
    CVT(x, xh, xl, NTOK * DMODEL);
    CVT(in_w, wih, wil, 4096 * DMODEL);
    gemm_mma<<<dim3(32, 32), 256, GEMM_SMEM>>>(xh, xl, wih, wil, xr,
                                               4096, DMODEL, DMODEL, DMODEL, 4096);
    // 2) conv + silu -> u
    conv_silu_kernel<<<EW_BLOCKS, 256>>>(xr, conv_w, conv_b, u);
    // 3) x_proj: xdbl = u @ xproj_w^T  (4096 x 96 x 2048)
    CVT(u, uh, ul, NTOK * DINNER);
    CVT(xproj_w, wxh, wxl, XDBL * DINNER);
    gemm_mma<<<dim3(1, 32), 256, GEMM_SMEM>>>(uh, ul, wxh, wxl, xdbl,
                                              XDBL, DINNER, DINNER, DINNER, XDBL);
    // 4) dt_proj: delta_raw = xdbl[:, :64] @ dtproj_w^T  (4096 x 2048 x 64)
    CVT(xdbl, xdh, xdl, NTOK * XDBL);
    CVT(dtproj_w, wdh, wdl, DINNER * DTRANK);
    gemm_mma<<<dim3(16, 32), 256, GEMM_SMEM>>>(xdh, xdl, wdh, wdl, delta,
                                               DINNER, DTRANK, XDBL, DTRANK, DINNER);
    // 5) softplus
    softplus_bias_kernel<<<EW_BLOCKS, 256>>>(delta, dtproj_b);
    // 6) scan
    scan_kernel<<<(NTOK * DSTATE) / 256, 256>>>(delta, u, xdbl, A_log, ys);
    // 7) gate
    gate_kernel<<<EW_BLOCKS, 256>>>(ys, u, Dvec, xr, yg);
    // 8) out_proj: out = yg @ out_w^T  (4096 x 1024 x 2048)
    CVT(yg, ygh, ygl, NTOK * DINNER);
    CVT(out_w, woh, wol, DMODEL * DINNER);
    gemm_mma<<<dim3(8, 32), 256, GEMM_SMEM>>>(ygh, ygl, woh, wol, out,
                                              DMODEL, DINNER, DINNER, DINNER, DMODEL);
#undef CVT
}